// round 2
// baseline (speedup 1.0000x reference)
#include <cuda_runtime.h>
#include <math.h>

#define Bq 16
#define NN 8192
#define WD 128
#define MD 32
#define NL 4
#define CHK 32
#define NPC (NN/CHK)   // 256

// ---- static device scratch (no cudaMalloc allowed) ----
__device__ float g_h0[Bq*NN*WD];            // 64 MB
__device__ float g_h1[Bq*NN*WD];            // 64 MB
__device__ float g_Fmn[2*MD*NN];            // [row][n]: rows 0..31 cos(2pi m n/N), 32..63 sin
__device__ float g_Fnm[NN*2*MD];            // [n][row]  (transposed copy for the forward DFT)
__device__ float g_Xp[Bq*CHK*2*MD*WD];      // split-K partials, 16.8 MB
__device__ float g_X[Bq*2*MD*WD];           // reduced spectra: rows 0..31 = sum h*cos, 32..63 = sum h*sin
__device__ float g_Y[Bq*2*MD*WD];           // mixed+scaled spectra: rows 0..31 Yr', 32..63 Yi'
__device__ float g_wrT[NL*MD*WD*WD];        // spec weights transposed to [l][m][i][o]
__device__ float g_wiT[NL*MD*WD*WD];

// ---- basis tables: cos/sin(2*pi*m*n/N) with exact argument reduction ----
__global__ void k_basis(){
  int idx = blockIdx.x*256 + threadIdx.x;
  if (idx >= MD*NN) return;
  int m = idx >> 13, n = idx & (NN-1);
  int p = (m*n) & (NN-1);                 // 2*pi*m*n/N = pi * (p/4096), exact in fp32
  float s, c;
  sincospif((float)p * (1.0f/4096.0f), &s, &c);
  g_Fmn[m*NN + n]        = c;
  g_Fmn[(MD+m)*NN + n]   = s;
  g_Fnm[n*64 + m]        = c;
  g_Fnm[n*64 + MD + m]   = s;
}

// ---- transpose spectral weights [l][i][o][m] -> [l][m][i][o] ----
__global__ void k_spec_t(const float* __restrict__ wr, const float* __restrict__ wi){
  int idx = blockIdx.x*256 + threadIdx.x;
  if (idx >= NL*MD*WD*WD) return;
  int o = idx & 127;
  int t = idx >> 7;
  int i = t & 127; t >>= 7;
  int m = t & 31;  int l = t >> 5;
  int src = ((l*WD + i)*WD + o)*MD + m;
  g_wrT[idx] = wr[src];
  g_wiT[idx] = wi[src];
}

// ---- fc0: h0[b,n,c] = x[b,n]*w[c] + b[c] ----
__global__ void k_fc0(const float* __restrict__ x, const float* __restrict__ w,
                      const float* __restrict__ bb){
  int idx = blockIdx.x*256 + threadIdx.x;      // < Bq*NN*WD
  int c = idx & 127; int bn = idx >> 7;
  g_h0[idx] = x[bn]*w[c] + bb[c];
}

// ---- forward DFT (split-K): per (chunk,b) block computes partial [64 x 128] ----
__global__ __launch_bounds__(128) void k_fwd(const float* __restrict__ h){
  int ck = blockIdx.x, b = blockIdx.y;
  int tid = threadIdx.x;
  int tx = tid & 15, ty = tid >> 4;
  int c0 = tx*8, r0 = ty*8;
  int n0 = ck*NPC;
  __shared__ float hs[16][128];
  __shared__ float fsm[16][64];
  float acc[8][8];
  #pragma unroll
  for (int u=0;u<8;u++){
    #pragma unroll
    for (int v=0;v<8;v++) acc[u][v]=0.f;
  }
  const float* hb = h + (size_t)b*NN*WD;
  for (int nt=0; nt<NPC; nt+=16){
    #pragma unroll
    for (int j=0;j<4;j++){
      int e = tid + j*128;
      int nn = e >> 5, c4 = e & 31;
      *(float4*)&hs[nn][c4*4] = *(const float4*)&hb[(size_t)(n0+nt+nn)*WD + c4*4];
    }
    #pragma unroll
    for (int j=0;j<2;j++){
      int e = tid + j*128;
      int nn = e >> 4, r4 = e & 15;
      *(float4*)&fsm[nn][r4*4] = *(const float4*)&g_Fnm[(size_t)(n0+nt+nn)*64 + r4*4];
    }
    __syncthreads();
    #pragma unroll
    for (int nn=0;nn<16;nn++){
      float f[8], hv[8];
      *(float4*)&f[0]  = *(float4*)&fsm[nn][r0];
      *(float4*)&f[4]  = *(float4*)&fsm[nn][r0+4];
      *(float4*)&hv[0] = *(float4*)&hs[nn][c0];
      *(float4*)&hv[4] = *(float4*)&hs[nn][c0+4];
      #pragma unroll
      for (int u=0;u<8;u++){
        #pragma unroll
        for (int v=0;v<8;v++) acc[u][v] += f[u]*hv[v];
      }
    }
    __syncthreads();
  }
  float* dst = g_Xp + (size_t)(b*CHK+ck)*64*WD;
  #pragma unroll
  for (int u=0;u<8;u++){
    *(float4*)&dst[(r0+u)*WD + c0]   = *(float4*)&acc[u][0];
    *(float4*)&dst[(r0+u)*WD + c0+4] = *(float4*)&acc[u][4];
  }
}

// ---- reduce split-K partials ----
__global__ void k_red(){
  int idx = blockIdx.x*256 + threadIdx.x;
  if (idx >= Bq*64*WD) return;
  int b = idx / (64*WD);
  int inner = idx - b*64*WD;
  const float* p = g_Xp + (size_t)b*CHK*64*WD + inner;
  float s = 0.f;
  #pragma unroll
  for (int c=0;c<CHK;c++) s += p[(size_t)c*64*WD];
  g_X[idx] = s;
}

// ---- spectral mix: Y = X * W (complex), with irfft scaling folded in ----
// Xr = sum h*cos (row m), S = sum h*sin (row 32+m), Xi = -S
// Yr = Xr*wr - Xi*wi = Xr*wr + S*wi ; Yi = Xr*wi + Xi*wr = Xr*wi - S*wr
__global__ __launch_bounds__(128) void k_mix(int l){
  int m = blockIdx.x, b = blockIdx.y;
  int o = threadIdx.x;
  __shared__ float xr[128], xs[128];
  xr[o] = g_X[(b*64+m)*WD + o];
  xs[o] = g_X[(b*64+MD+m)*WD + o];
  __syncthreads();
  const float* wr = g_wrT + ((size_t)l*MD + m)*WD*WD + o;
  const float* wi = g_wiT + ((size_t)l*MD + m)*WD*WD + o;
  float yr=0.f, yi=0.f;
  #pragma unroll 8
  for (int i=0;i<WD;i++){
    float a = xr[i], s = xs[i];
    float r = wr[(size_t)i*WD], q = wi[(size_t)i*WD];
    yr += a*r + s*q;
    yi += a*q - s*r;
  }
  float alpha = (m==0) ? (1.0f/NN) : (2.0f/NN);
  g_Y[(b*64+m)*WD+o]    = alpha*yr;
  g_Y[(b*64+MD+m)*WD+o] = alpha*yi;
}

// ---- fused layer: h_new = gelu?( h@skip_w + irfft(Y) + skip_b ) as K=192 GEMM ----
// K 0..127 : A = h[b,n,k],          W = skip_w[k][o]
// K 128..159: A = cos(2pi m n/N),   W = Yr'[b][m][o]        (m = k-128)
// K 160..191: A = sin(2pi m n/N),   W = -Yi'[b][m][o]       (m = k-160)
__global__ __launch_bounds__(256) void k_layer(const float* __restrict__ h,
      const float* __restrict__ skw, const float* __restrict__ skb,
      float* __restrict__ outp, int dogelu){
  int b = blockIdx.y;
  int n0 = blockIdx.x * 64;
  int tid = threadIdx.x;
  int to = tid & 15, tn = tid >> 4;
  int o0 = to*8, nb = tn*4;
  __shared__ float As[16][64];
  __shared__ float Ws[16][128];
  float acc[4][8];
  #pragma unroll
  for (int u=0;u<4;u++){
    #pragma unroll
    for (int v=0;v<8;v++) acc[u][v]=0.f;
  }
  const float* hb = h + (size_t)b*NN*WD;
  for (int k0=0; k0<192; k0+=16){
    if (k0 < 128){
      int nn = tid >> 2, kq = tid & 3;
      float4 v = *(const float4*)&hb[(size_t)(n0+nn)*WD + k0 + kq*4];
      As[kq*4+0][nn]=v.x; As[kq*4+1][nn]=v.y; As[kq*4+2][nn]=v.z; As[kq*4+3][nn]=v.w;
      #pragma unroll
      for (int j=0;j<8;j++){
        int e = tid + j*256;
        int kk = e >> 7, o = e & 127;
        Ws[kk][o] = skw[(k0+kk)*WD + o];
      }
    } else {
      int ry = k0 - 128;                       // row into basis/Y (0..63)
      #pragma unroll
      for (int j=0;j<4;j++){
        int e = tid + j*256;
        int kk = e >> 6, nn2 = e & 63;
        As[kk][nn2] = g_Fmn[(size_t)(ry+kk)*NN + n0 + nn2];
      }
      float sgn = (k0 >= 160) ? -1.f : 1.f;    // minus for the Yi'*sin part
      #pragma unroll
      for (int j=0;j<8;j++){
        int e = tid + j*256;
        int kk = e >> 7, o = e & 127;
        Ws[kk][o] = sgn * g_Y[(size_t)(b*64 + ry + kk)*WD + o];
      }
    }
    __syncthreads();
    #pragma unroll
    for (int kk=0;kk<16;kk++){
      float av[4], wv[8];
      *(float4*)&av[0] = *(float4*)&As[kk][nb];
      *(float4*)&wv[0] = *(float4*)&Ws[kk][o0];
      *(float4*)&wv[4] = *(float4*)&Ws[kk][o0+4];
      #pragma unroll
      for (int u=0;u<4;u++){
        #pragma unroll
        for (int v=0;v<8;v++) acc[u][v] += av[u]*wv[v];
      }
    }
    __syncthreads();
  }
  #pragma unroll
  for (int u=0;u<4;u++){
    int n = n0 + nb + u;
    float res[8];
    #pragma unroll
    for (int v=0;v<8;v++){
      float val = acc[u][v] + skb[o0+v];
      if (dogelu) val = 0.5f*val*(1.0f + erff(val*0.70710678118654752f));
      res[v] = val;
    }
    float* op = outp + ((size_t)b*NN + n)*WD + o0;
    *(float4*)&op[0] = *(float4*)&res[0];
    *(float4*)&op[4] = *(float4*)&res[4];
  }
}

// ---- head: out = gelu(h@fc1_w + fc1_b) @ fc2_w + fc2_b ----
__global__ __launch_bounds__(128) void k_head(const float* __restrict__ h,
      const float* __restrict__ w1, const float* __restrict__ b1v,
      const float* __restrict__ w2, const float* __restrict__ b2v,
      float* __restrict__ out){
  int row0 = blockIdx.x * 32;
  int j = threadIdx.x;
  __shared__ float hs[32][128];
  #pragma unroll
  for (int r=0;r<32;r++)
    hs[r][j] = h[(size_t)(row0+r)*WD + j];
  __syncthreads();
  float acc[32];
  #pragma unroll
  for (int r=0;r<32;r++) acc[r] = 0.f;
  #pragma unroll 4
  for (int i=0;i<WD;i++){
    float w = w1[(size_t)i*WD + j];
    #pragma unroll
    for (int r=0;r<32;r++) acc[r] += hs[r][i]*w;
  }
  float bb = b1v[j], w2v = w2[j];
  int lane = j & 31, wid = j >> 5;
  __shared__ float part[32][4];
  #pragma unroll
  for (int r=0;r<32;r++){
    float val = acc[r] + bb;
    val = 0.5f*val*(1.0f + erff(val*0.70710678118654752f));
    float s = val * w2v;
    s += __shfl_xor_sync(0xffffffffu, s, 16);
    s += __shfl_xor_sync(0xffffffffu, s, 8);
    s += __shfl_xor_sync(0xffffffffu, s, 4);
    s += __shfl_xor_sync(0xffffffffu, s, 2);
    s += __shfl_xor_sync(0xffffffffu, s, 1);
    if (lane == 0) part[r][wid] = s;
  }
  __syncthreads();
  if (j < 32)
    out[row0 + j] = part[j][0]+part[j][1]+part[j][2]+part[j][3] + b2v[0];
}

extern "C" void kernel_launch(void* const* d_in, const int* in_sizes, int n_in,
                              void* d_out, int out_size){
  const float* x       = (const float*)d_in[0];
  const float* fc0_w   = (const float*)d_in[1];
  const float* fc0_b   = (const float*)d_in[2];
  const float* spec_wr = (const float*)d_in[3];
  const float* spec_wi = (const float*)d_in[4];
  const float* skip_w  = (const float*)d_in[5];
  const float* skip_b  = (const float*)d_in[6];
  const float* fc1_w   = (const float*)d_in[7];
  const float* fc1_b   = (const float*)d_in[8];
  const float* fc2_w   = (const float*)d_in[9];
  const float* fc2_b   = (const float*)d_in[10];
  float* out = (float*)d_out;
  (void)in_sizes; (void)n_in; (void)out_size;

  void *p0, *p1;
  cudaGetSymbolAddress(&p0, g_h0);
  cudaGetSymbolAddress(&p1, g_h1);
  float* hin  = (float*)p0;
  float* hout = (float*)p1;

  k_basis<<<(MD*NN + 255)/256, 256>>>();
  k_spec_t<<<(NL*MD*WD*WD + 255)/256, 256>>>(spec_wr, spec_wi);
  k_fc0<<<(Bq*NN*WD)/256, 256>>>(x, fc0_w, fc0_b);

  for (int l=0; l<NL; l++){
    k_fwd<<<dim3(CHK, Bq), 128>>>(hin);
    k_red<<<(Bq*64*WD + 255)/256, 256>>>();
    k_mix<<<dim3(MD, Bq), 128>>>(l);
    k_layer<<<dim3(NN/64, Bq), 256>>>(hin,
        skip_w + (size_t)l*WD*WD, skip_b + (size_t)l*WD, hout, (l < NL-1) ? 1 : 0);
    float* t = hin; hin = hout; hout = t;
  }
  k_head<<<(Bq*NN)/32, 128>>>(hin, fc1_w, fc1_b, fc2_w, fc2_b, out);
}

// round 3
// speedup vs baseline: 1.5329x; 1.5329x over previous
#include <cuda_runtime.h>
#include <cuda_bf16.h>
#include <math.h>

#define Bq 16
#define NN 8192
#define WD 128
#define MD 32
#define NL 4
#define CHK 32
#define NPC (NN/CHK)   // 256
#define PCH 36         // smem pitch (bf16 elems) = 32 + 4 pad -> conflict-free frag loads

typedef __nv_bfloat16 bf;

// ---- static device scratch ----
__device__ float g_h0[Bq*NN*WD];
__device__ float g_h1[Bq*NN*WD];
__device__ bf    g_Fmn_h[64*NN];   // [row r][n]  r<32: cos, r>=32: sin  (bf16 hi)
__device__ bf    g_Fmn_l[64*NN];   // (bf16 lo residual)
__device__ bf    g_Fnm_h[NN*64];   // [n][row r]  transposed copy
__device__ bf    g_Fnm_l[NN*64];
__device__ float g_Xp[Bq*CHK*64*WD];
__device__ float g_X[Bq*64*WD];
__device__ float g_Y[Bq*64*WD];
__device__ float g_wrT[NL*MD*WD*WD];
__device__ float g_wiT[NL*MD*WD*WD];

__device__ __forceinline__ void f2bb(float x, bf &h, bf &l){
  h = __float2bfloat16(x);
  l = __float2bfloat16(x - __bfloat162float(h));
}
__device__ __forceinline__ unsigned ldu32(const bf* p){ return *(const unsigned*)p; }
__device__ __forceinline__ float gelu_f(float v){
  return 0.5f*v*(1.0f + erff(v*0.70710678118654752f));
}
__device__ __forceinline__ void mma16816(float* d, const unsigned* a, const unsigned* b){
  asm volatile("mma.sync.aligned.m16n8k16.row.col.f32.bf16.bf16.f32 "
    "{%0,%1,%2,%3},{%4,%5,%6,%7},{%8,%9},{%0,%1,%2,%3};\n"
    : "+f"(d[0]),"+f"(d[1]),"+f"(d[2]),"+f"(d[3])
    : "r"(a[0]),"r"(a[1]),"r"(a[2]),"r"(a[3]),"r"(b[0]),"r"(b[1]));
}

// ---- basis tables as bf16 hi/lo, exact fp32 argument reduction ----
__global__ void k_basis(){
  int idx = blockIdx.x*256 + threadIdx.x;
  if (idx >= MD*NN) return;
  int m = idx >> 13, n = idx & (NN-1);
  int p = (m*n) & (NN-1);
  float s, c;
  sincospif((float)p * (1.0f/4096.0f), &s, &c);
  bf ch,cl,sh,sl;
  f2bb(c,ch,cl); f2bb(s,sh,sl);
  g_Fmn_h[(size_t)m*NN + n]      = ch;  g_Fmn_l[(size_t)m*NN + n]      = cl;
  g_Fmn_h[(size_t)(MD+m)*NN + n] = sh;  g_Fmn_l[(size_t)(MD+m)*NN + n] = sl;
  g_Fnm_h[(size_t)n*64 + m]      = ch;  g_Fnm_l[(size_t)n*64 + m]      = cl;
  g_Fnm_h[(size_t)n*64 + MD + m] = sh;  g_Fnm_l[(size_t)n*64 + MD + m] = sl;
}

// ---- transpose spectral weights [l][i][o][m] -> [l][m][i][o] ----
__global__ void k_spec_t(const float* __restrict__ wr, const float* __restrict__ wi){
  int idx = blockIdx.x*256 + threadIdx.x;
  if (idx >= NL*MD*WD*WD) return;
  int o = idx & 127;
  int t = idx >> 7;
  int i = t & 127; t >>= 7;
  int m = t & 31;  int l = t >> 5;
  int src = ((l*WD + i)*WD + o)*MD + m;
  g_wrT[idx] = wr[src];
  g_wiT[idx] = wi[src];
}

// ---- fc0 ----
__global__ void k_fc0(const float* __restrict__ x, const float* __restrict__ w,
                      const float* __restrict__ bb){
  int idx = blockIdx.x*256 + threadIdx.x;
  int c = idx & 127; int bn = idx >> 7;
  g_h0[idx] = x[bn]*w[c] + bb[c];
}

// ---- forward DFT via tensor cores (split-K over 32 chunks) ----
// X[r][c] = sum_n F[r][n] * h[n][c];  M=64 (r), N=128 (c), K=256 per block
__global__ __launch_bounds__(128) void k_fwd(const float* __restrict__ h){
  int ck = blockIdx.x, b = blockIdx.y;
  int tid = threadIdx.x, wid = tid>>5, lane = tid&31, g = lane>>2, tg = lane&3;
  int n_base = wid*32;
  __shared__ bf Ah[64*PCH], Al[64*PCH], Bh[128*PCH], Bl[128*PCH];
  float acc[4][4][4];
  #pragma unroll
  for (int mi=0;mi<4;mi++)
    #pragma unroll
    for (int ni=0;ni<4;ni++)
      #pragma unroll
      for (int q=0;q<4;q++) acc[mi][ni][q]=0.f;
  const float* hb = h + (size_t)b*NN*WD;
  int n0 = ck*NPC;
  for (int nt=0; nt<NPC; nt+=32){
    // A: F rows [64][32] (precomputed bf16 hi/lo, straight copy)
    #pragma unroll
    for (int j=0;j<8;j++){
      int e=tid+j*128; int row=e>>4, q=e&15;
      *(unsigned*)&Ah[row*PCH+q*2] = *(const unsigned*)&g_Fmn_h[(size_t)row*NN + n0+nt + q*2];
      *(unsigned*)&Al[row*PCH+q*2] = *(const unsigned*)&g_Fmn_l[(size_t)row*NN + n0+nt + q*2];
    }
    // B: h chunk [32 k][128 c] -> BT[c][k] with hi/lo convert
    #pragma unroll
    for (int j=0;j<8;j++){
      int e=tid+j*128; int kk=e>>5, oq=e&31;
      float4 v = *(const float4*)&hb[(size_t)(n0+nt+kk)*WD + oq*4];
      bf hh,ll;
      f2bb(v.x,hh,ll); Bh[(oq*4+0)*PCH+kk]=hh; Bl[(oq*4+0)*PCH+kk]=ll;
      f2bb(v.y,hh,ll); Bh[(oq*4+1)*PCH+kk]=hh; Bl[(oq*4+1)*PCH+kk]=ll;
      f2bb(v.z,hh,ll); Bh[(oq*4+2)*PCH+kk]=hh; Bl[(oq*4+2)*PCH+kk]=ll;
      f2bb(v.w,hh,ll); Bh[(oq*4+3)*PCH+kk]=hh; Bl[(oq*4+3)*PCH+kk]=ll;
    }
    __syncthreads();
    #pragma unroll
    for (int ks=0;ks<2;ks++){
      int kb = ks*16;
      unsigned af[4][4], bfr[4][2], tf[4][2];
      #pragma unroll
      for (int mi=0;mi<4;mi++){
        const bf* base = Ah + (mi*16+g)*PCH + kb + tg*2;
        af[mi][0]=ldu32(base); af[mi][1]=ldu32(base+8*PCH);
        af[mi][2]=ldu32(base+8); af[mi][3]=ldu32(base+8*PCH+8);
      }
      #pragma unroll
      for (int ni=0;ni<4;ni++){
        const bf* base = Bh + (n_base+ni*8+g)*PCH + kb + tg*2;
        bfr[ni][0]=ldu32(base); bfr[ni][1]=ldu32(base+8);
      }
      #pragma unroll
      for (int mi=0;mi<4;mi++)
        #pragma unroll
        for (int ni=0;ni<4;ni++) mma16816(acc[mi][ni], af[mi], bfr[ni]);   // hiA*hiB
      #pragma unroll
      for (int ni=0;ni<4;ni++){
        const bf* base = Bl + (n_base+ni*8+g)*PCH + kb + tg*2;
        tf[ni][0]=ldu32(base); tf[ni][1]=ldu32(base+8);
      }
      #pragma unroll
      for (int mi=0;mi<4;mi++)
        #pragma unroll
        for (int ni=0;ni<4;ni++) mma16816(acc[mi][ni], af[mi], tf[ni]);    // hiA*loB
      #pragma unroll
      for (int mi=0;mi<4;mi++){
        const bf* base = Al + (mi*16+g)*PCH + kb + tg*2;
        af[mi][0]=ldu32(base); af[mi][1]=ldu32(base+8*PCH);
        af[mi][2]=ldu32(base+8); af[mi][3]=ldu32(base+8*PCH+8);
      }
      #pragma unroll
      for (int mi=0;mi<4;mi++)
        #pragma unroll
        for (int ni=0;ni<4;ni++) mma16816(acc[mi][ni], af[mi], bfr[ni]);   // loA*hiB
    }
    __syncthreads();
  }
  float* dst = g_Xp + (size_t)(b*CHK+ck)*64*WD;
  #pragma unroll
  for (int ni=0;ni<4;ni++){
    int col = n_base + ni*8 + tg*2;
    #pragma unroll
    for (int mi=0;mi<4;mi++){
      int r0 = mi*16 + g;
      *(float2*)&dst[r0*WD+col]     = make_float2(acc[mi][ni][0], acc[mi][ni][1]);
      *(float2*)&dst[(r0+8)*WD+col] = make_float2(acc[mi][ni][2], acc[mi][ni][3]);
    }
  }
}

// ---- reduce split-K partials ----
__global__ void k_red(){
  int idx = blockIdx.x*256 + threadIdx.x;
  if (idx >= Bq*64*WD) return;
  int b = idx / (64*WD);
  int inner = idx - b*64*WD;
  const float* p = g_Xp + (size_t)b*CHK*64*WD + inner;
  float s = 0.f;
  #pragma unroll
  for (int c=0;c<CHK;c++) s += p[(size_t)c*64*WD];
  g_X[idx] = s;
}

// ---- spectral mix (fp32 SIMT, small) ----
__global__ __launch_bounds__(128) void k_mix(int l){
  int m = blockIdx.x, b = blockIdx.y;
  int o = threadIdx.x;
  __shared__ float xr[128], xs[128];
  xr[o] = g_X[(b*64+m)*WD + o];
  xs[o] = g_X[(b*64+MD+m)*WD + o];
  __syncthreads();
  const float* wr = g_wrT + ((size_t)l*MD + m)*WD*WD + o;
  const float* wi = g_wiT + ((size_t)l*MD + m)*WD*WD + o;
  float yr=0.f, yi=0.f;
  #pragma unroll 8
  for (int i=0;i<WD;i++){
    float a = xr[i], s = xs[i];
    float r = wr[(size_t)i*WD], q = wi[(size_t)i*WD];
    yr += a*r + s*q;
    yi += a*q - s*r;
  }
  float alpha = (m==0) ? (1.0f/NN) : (2.0f/NN);
  g_Y[(b*64+m)*WD+o]    = alpha*yr;
  g_Y[(b*64+MD+m)*WD+o] = alpha*yi;
}

// ---- fused layer (tensor cores): h_new = gelu?( h@skip_w + irfft(Y) + skip_b )
// A[n][k]: k<128 -> h row; k>=128 -> Fnm row (contiguous!). B[k][o]: skip_w / +-Y.
__global__ __launch_bounds__(256) void k_layer(const float* __restrict__ h,
      const float* __restrict__ skw, const float* __restrict__ skb,
      float* __restrict__ outp, int dogelu){
  int b = blockIdx.y;
  int n0 = blockIdx.x * 128;
  int tid = threadIdx.x, wid = tid>>5, lane = tid&31, g = lane>>2, tg = lane&3;
  int m_base = (wid>>2)*64, n_base = (wid&3)*32;
  __shared__ bf Ah[128*PCH], Al[128*PCH], Bh[128*PCH], Bl[128*PCH];
  float acc[4][4][4];
  #pragma unroll
  for (int mi=0;mi<4;mi++)
    #pragma unroll
    for (int ni=0;ni<4;ni++)
      #pragma unroll
      for (int q=0;q<4;q++) acc[mi][ni][q]=0.f;
  const float* hb = h + (size_t)b*NN*WD;
  #pragma unroll 1
  for (int c6=0;c6<6;c6++){
    int k0 = c6*32;
    if (k0 < 128){
      #pragma unroll
      for (int j=0;j<4;j++){
        int e=tid+j*256; int row=e>>3, kq=e&7;
        float4 v = *(const float4*)&hb[(size_t)(n0+row)*WD + k0 + kq*4];
        bf hh,ll;
        f2bb(v.x,hh,ll); Ah[row*PCH+kq*4+0]=hh; Al[row*PCH+kq*4+0]=ll;
        f2bb(v.y,hh,ll); Ah[row*PCH+kq*4+1]=hh; Al[row*PCH+kq*4+1]=ll;
        f2bb(v.z,hh,ll); Ah[row*PCH+kq*4+2]=hh; Al[row*PCH+kq*4+2]=ll;
        f2bb(v.w,hh,ll); Ah[row*PCH+kq*4+3]=hh; Al[row*PCH+kq*4+3]=ll;
      }
      #pragma unroll
      for (int j=0;j<4;j++){
        int e=tid+j*256; int kk=e>>5, oq=e&31;
        float4 v = *(const float4*)&skw[(size_t)(k0+kk)*WD + oq*4];
        bf hh,ll;
        f2bb(v.x,hh,ll); Bh[(oq*4+0)*PCH+kk]=hh; Bl[(oq*4+0)*PCH+kk]=ll;
        f2bb(v.y,hh,ll); Bh[(oq*4+1)*PCH+kk]=hh; Bl[(oq*4+1)*PCH+kk]=ll;
        f2bb(v.z,hh,ll); Bh[(oq*4+2)*PCH+kk]=hh; Bl[(oq*4+2)*PCH+kk]=ll;
        f2bb(v.w,hh,ll); Bh[(oq*4+3)*PCH+kk]=hh; Bl[(oq*4+3)*PCH+kk]=ll;
      }
    } else {
      int jr = k0 - 128;
      #pragma unroll
      for (int j=0;j<8;j++){
        int e=tid+j*256; int row=e>>4, q=e&15;
        *(unsigned*)&Ah[row*PCH+q*2] = *(const unsigned*)&g_Fnm_h[(size_t)(n0+row)*64 + jr + q*2];
        *(unsigned*)&Al[row*PCH+q*2] = *(const unsigned*)&g_Fnm_l[(size_t)(n0+row)*64 + jr + q*2];
      }
      #pragma unroll
      for (int j=0;j<4;j++){
        int e=tid+j*256; int kk=e>>5, oq=e&31;
        int ja = jr + kk;
        float sgn = (ja >= MD) ? -1.f : 1.f;
        float4 v = *(const float4*)&g_Y[(size_t)(b*64+ja)*WD + oq*4];
        bf hh,ll;
        f2bb(sgn*v.x,hh,ll); Bh[(oq*4+0)*PCH+kk]=hh; Bl[(oq*4+0)*PCH+kk]=ll;
        f2bb(sgn*v.y,hh,ll); Bh[(oq*4+1)*PCH+kk]=hh; Bl[(oq*4+1)*PCH+kk]=ll;
        f2bb(sgn*v.z,hh,ll); Bh[(oq*4+2)*PCH+kk]=hh; Bl[(oq*4+2)*PCH+kk]=ll;
        f2bb(sgn*v.w,hh,ll); Bh[(oq*4+3)*PCH+kk]=hh; Bl[(oq*4+3)*PCH+kk]=ll;
      }
    }
    __syncthreads();
    #pragma unroll
    for (int ks=0;ks<2;ks++){
      int kb = ks*16;
      unsigned af[4][4], bfr[4][2], tf[4][2];
      #pragma unroll
      for (int mi=0;mi<4;mi++){
        const bf* base = Ah + (m_base+mi*16+g)*PCH + kb + tg*2;
        af[mi][0]=ldu32(base); af[mi][1]=ldu32(base+8*PCH);
        af[mi][2]=ldu32(base+8); af[mi][3]=ldu32(base+8*PCH+8);
      }
      #pragma unroll
      for (int ni=0;ni<4;ni++){
        const bf* base = Bh + (n_base+ni*8+g)*PCH + kb + tg*2;
        bfr[ni][0]=ldu32(base); bfr[ni][1]=ldu32(base+8);
      }
      #pragma unroll
      for (int mi=0;mi<4;mi++)
        #pragma unroll
        for (int ni=0;ni<4;ni++) mma16816(acc[mi][ni], af[mi], bfr[ni]);
      #pragma unroll
      for (int ni=0;ni<4;ni++){
        const bf* base = Bl + (n_base+ni*8+g)*PCH + kb + tg*2;
        tf[ni][0]=ldu32(base); tf[ni][1]=ldu32(base+8);
      }
      #pragma unroll
      for (int mi=0;mi<4;mi++)
        #pragma unroll
        for (int ni=0;ni<4;ni++) mma16816(acc[mi][ni], af[mi], tf[ni]);
      #pragma unroll
      for (int mi=0;mi<4;mi++){
        const bf* base = Al + (m_base+mi*16+g)*PCH + kb + tg*2;
        af[mi][0]=ldu32(base); af[mi][1]=ldu32(base+8*PCH);
        af[mi][2]=ldu32(base+8); af[mi][3]=ldu32(base+8*PCH+8);
      }
      #pragma unroll
      for (int mi=0;mi<4;mi++)
        #pragma unroll
        for (int ni=0;ni<4;ni++) mma16816(acc[mi][ni], af[mi], bfr[ni]);
    }
    __syncthreads();
  }
  #pragma unroll
  for (int ni=0;ni<4;ni++){
    int col = n_base + ni*8 + tg*2;
    float bia0 = skb[col], bia1 = skb[col+1];
    #pragma unroll
    for (int mi=0;mi<4;mi++){
      int r0 = n0 + m_base + mi*16 + g;
      float v0=acc[mi][ni][0]+bia0, v1=acc[mi][ni][1]+bia1;
      float v2=acc[mi][ni][2]+bia0, v3=acc[mi][ni][3]+bia1;
      if (dogelu){ v0=gelu_f(v0); v1=gelu_f(v1); v2=gelu_f(v2); v3=gelu_f(v3); }
      *(float2*)&outp[((size_t)b*NN + r0)*WD + col]     = make_float2(v0,v1);
      *(float2*)&outp[((size_t)b*NN + r0 + 8)*WD + col] = make_float2(v2,v3);
    }
  }
}

// ---- head: out = gelu(h@fc1_w + fc1_b) @ fc2_w + fc2_b  (fused, tensor cores)
__global__ __launch_bounds__(256) void k_head(const float* __restrict__ h,
      const float* __restrict__ w1, const float* __restrict__ b1v,
      const float* __restrict__ w2, const float* __restrict__ b2v,
      float* __restrict__ out){
  int row0 = blockIdx.x * 128;
  int tid = threadIdx.x, wid = tid>>5, lane = tid&31, g = lane>>2, tg = lane&3;
  int m_base = (wid>>2)*64, n_base = (wid&3)*32;
  __shared__ bf Ah[128*PCH], Al[128*PCH], Bh[128*PCH], Bl[128*PCH];
  __shared__ float red[4][128];
  float acc[4][4][4];
  #pragma unroll
  for (int mi=0;mi<4;mi++)
    #pragma unroll
    for (int ni=0;ni<4;ni++)
      #pragma unroll
      for (int q=0;q<4;q++) acc[mi][ni][q]=0.f;
  #pragma unroll 1
  for (int c4=0;c4<4;c4++){
    int k0 = c4*32;
    #pragma unroll
    for (int j=0;j<4;j++){
      int e=tid+j*256; int row=e>>3, kq=e&7;
      float4 v = *(const float4*)&h[(size_t)(row0+row)*WD + k0 + kq*4];
      bf hh,ll;
      f2bb(v.x,hh,ll); Ah[row*PCH+kq*4+0]=hh; Al[row*PCH+kq*4+0]=ll;
      f2bb(v.y,hh,ll); Ah[row*PCH+kq*4+1]=hh; Al[row*PCH+kq*4+1]=ll;
      f2bb(v.z,hh,ll); Ah[row*PCH+kq*4+2]=hh; Al[row*PCH+kq*4+2]=ll;
      f2bb(v.w,hh,ll); Ah[row*PCH+kq*4+3]=hh; Al[row*PCH+kq*4+3]=ll;
    }
    #pragma unroll
    for (int j=0;j<4;j++){
      int e=tid+j*256; int kk=e>>5, oq=e&31;
      float4 v = *(const float4*)&w1[(size_t)(k0+kk)*WD + oq*4];
      bf hh,ll;
      f2bb(v.x,hh,ll); Bh[(oq*4+0)*PCH+kk]=hh; Bl[(oq*4+0)*PCH+kk]=ll;
      f2bb(v.y,hh,ll); Bh[(oq*4+1)*PCH+kk]=hh; Bl[(oq*4+1)*PCH+kk]=ll;
      f2bb(v.z,hh,ll); Bh[(oq*4+2)*PCH+kk]=hh; Bl[(oq*4+2)*PCH+kk]=ll;
      f2bb(v.w,hh,ll); Bh[(oq*4+3)*PCH+kk]=hh; Bl[(oq*4+3)*PCH+kk]=ll;
    }
    __syncthreads();
    #pragma unroll
    for (int ks=0;ks<2;ks++){
      int kb = ks*16;
      unsigned af[4][4], bfr[4][2], tf[4][2];
      #pragma unroll
      for (int mi=0;mi<4;mi++){
        const bf* base = Ah + (m_base+mi*16+g)*PCH + kb + tg*2;
        af[mi][0]=ldu32(base); af[mi][1]=ldu32(base+8*PCH);
        af[mi][2]=ldu32(base+8); af[mi][3]=ldu32(base+8*PCH+8);
      }
      #pragma unroll
      for (int ni=0;ni<4;ni++){
        const bf* base = Bh + (n_base+ni*8+g)*PCH + kb + tg*2;
        bfr[ni][0]=ldu32(base); bfr[ni][1]=ldu32(base+8);
      }
      #pragma unroll
      for (int mi=0;mi<4;mi++)
        #pragma unroll
        for (int ni=0;ni<4;ni++) mma16816(acc[mi][ni], af[mi], bfr[ni]);
      #pragma unroll
      for (int ni=0;ni<4;ni++){
        const bf* base = Bl + (n_base+ni*8+g)*PCH + kb + tg*2;
        tf[ni][0]=ldu32(base); tf[ni][1]=ldu32(base+8);
      }
      #pragma unroll
      for (int mi=0;mi<4;mi++)
        #pragma unroll
        for (int ni=0;ni<4;ni++) mma16816(acc[mi][ni], af[mi], tf[ni]);
      #pragma unroll
      for (int mi=0;mi<4;mi++){
        const bf* base = Al + (m_base+mi*16+g)*PCH + kb + tg*2;
        af[mi][0]=ldu32(base); af[mi][1]=ldu32(base+8*PCH);
        af[mi][2]=ldu32(base+8); af[mi][3]=ldu32(base+8*PCH+8);
      }
      #pragma unroll
      for (int mi=0;mi<4;mi++)
        #pragma unroll
        for (int ni=0;ni<4;ni++) mma16816(acc[mi][ni], af[mi], bfr[ni]);
    }
    __syncthreads();
  }
  // epilogue: gelu + weighted column reduction (deterministic shuffle tree)
  float s[4][2];
  #pragma unroll
  for (int mi=0;mi<4;mi++){ s[mi][0]=0.f; s[mi][1]=0.f; }
  #pragma unroll
  for (int ni=0;ni<4;ni++){
    int col = n_base + ni*8 + tg*2;
    float bia0=b1v[col], bia1=b1v[col+1];
    float w20=w2[col],  w21=w2[col+1];
    #pragma unroll
    for (int mi=0;mi<4;mi++){
      s[mi][0] += gelu_f(acc[mi][ni][0]+bia0)*w20 + gelu_f(acc[mi][ni][1]+bia1)*w21;
      s[mi][1] += gelu_f(acc[mi][ni][2]+bia0)*w20 + gelu_f(acc[mi][ni][3]+bia1)*w21;
    }
  }
  #pragma unroll
  for (int mi=0;mi<4;mi++){
    #pragma unroll
    for (int q=0;q<2;q++){
      s[mi][q] += __shfl_xor_sync(0xffffffffu, s[mi][q], 1);
      s[mi][q] += __shfl_xor_sync(0xffffffffu, s[mi][q], 2);
    }
  }
  if (tg == 0){
    int wn = wid & 3;
    #pragma unroll
    for (int mi=0;mi<4;mi++){
      red[wn][m_base+mi*16+g]   = s[mi][0];
      red[wn][m_base+mi*16+g+8] = s[mi][1];
    }
  }
  __syncthreads();
  if (tid < 128)
    out[row0 + tid] = red[0][tid]+red[1][tid]+red[2][tid]+red[3][tid] + b2v[0];
}

extern "C" void kernel_launch(void* const* d_in, const int* in_sizes, int n_in,
                              void* d_out, int out_size){
  const float* x       = (const float*)d_in[0];
  const float* fc0_w   = (const float*)d_in[1];
  const float* fc0_b   = (const float*)d_in[2];
  const float* spec_wr = (const float*)d_in[3];
  const float* spec_wi = (const float*)d_in[4];
  const float* skip_w  = (const float*)d_in[5];
  const float* skip_b  = (const float*)d_in[6];
  const float* fc1_w   = (const float*)d_in[7];
  const float* fc1_b   = (const float*)d_in[8];
  const float* fc2_w   = (const float*)d_in[9];
  const float* fc2_b   = (const float*)d_in[10];
  float* out = (float*)d_out;
  (void)in_sizes; (void)n_in; (void)out_size;

  void *p0, *p1;
  cudaGetSymbolAddress(&p0, g_h0);
  cudaGetSymbolAddress(&p1, g_h1);
  float* hin  = (float*)p0;
  float* hout = (float*)p1;

  k_basis<<<(MD*NN + 255)/256, 256>>>();
  k_spec_t<<<(NL*MD*WD*WD + 255)/256, 256>>>(spec_wr, spec_wi);
  k_fc0<<<(Bq*NN*WD)/256, 256>>>(x, fc0_w, fc0_b);

  for (int l=0; l<NL; l++){
    k_fwd<<<dim3(CHK, Bq), 128>>>(hin);
    k_red<<<(Bq*64*WD + 255)/256, 256>>>();
    k_mix<<<dim3(MD, Bq), 128>>>(l);
    k_layer<<<dim3(NN/128, Bq), 256>>>(hin,
        skip_w + (size_t)l*WD*WD, skip_b + (size_t)l*WD, hout, (l < NL-1) ? 1 : 0);
    float* t = hin; hin = hout; hout = t;
  }
  k_head<<<(Bq*NN)/128, 256>>>(hin, fc1_w, fc1_b, fc2_w, fc2_b, out);
}

// round 4
// speedup vs baseline: 2.9816x; 1.9450x over previous
#include <cuda_runtime.h>
#include <cuda_bf16.h>
#include <math.h>

#define Bq 16
#define NN 8192
#define WD 128
#define MD 32
#define NL 4
#define CHK 32
#define NPC (NN/CHK)   // 256
#define PCHA 40        // A smem pitch (bf16 elems): 16B-aligned rows, conflict-free ldmatrix
#define PCHB 136       // B smem pitch

typedef __nv_bfloat16 bf;

// ---- static device scratch ----
__device__ __align__(16) bf g_hh0[Bq*NN*WD];
__device__ __align__(16) bf g_hl0[Bq*NN*WD];
__device__ __align__(16) bf g_hh1[Bq*NN*WD];
__device__ __align__(16) bf g_hl1[Bq*NN*WD];
__device__ __align__(16) bf g_FblkH[64*NN];   // [n-chunk32][64 r][32]  (k_fwd A, blocked)
__device__ __align__(16) bf g_FblkL[64*NN];
__device__ __align__(16) bf g_FnmH[NN*64];    // [n][r]                 (k_layer A tail)
__device__ __align__(16) bf g_FnmL[NN*64];
__device__ __align__(16) bf g_skwH[NL*WD*WD]; // [l][k][o] bf16 of skip_w
__device__ __align__(16) bf g_skwL[NL*WD*WD];
__device__ __align__(16) bf g_w1H[WD*WD];     // [k][o] of fc1_w
__device__ __align__(16) bf g_w1L[WD*WD];
__device__ __align__(16) bf g_YbH[Bq*64*WD];  // [b][j][o]: j<32: Yr', j>=32: -Yi'
__device__ __align__(16) bf g_YbL[Bq*64*WD];
__device__ float g_Xp[Bq*CHK*64*WD];          // split-K partials (fp32)
__device__ float g_wrT[NL*MD*WD*WD];
__device__ float g_wiT[NL*MD*WD*WD];

__device__ __forceinline__ void f2bb(float x, bf &h, bf &l){
  h = __float2bfloat16(x);
  l = __float2bfloat16(x - __bfloat162float(h));
}
__device__ __forceinline__ float gelu_f(float v){
  return 0.5f*v*(1.0f + erff(v*0.70710678118654752f));
}
__device__ __forceinline__ void mma16816(float* d, const unsigned* a, const unsigned* b){
  asm volatile("mma.sync.aligned.m16n8k16.row.col.f32.bf16.bf16.f32 "
    "{%0,%1,%2,%3},{%4,%5,%6,%7},{%8,%9},{%0,%1,%2,%3};\n"
    : "+f"(d[0]),"+f"(d[1]),"+f"(d[2]),"+f"(d[3])
    : "r"(a[0]),"r"(a[1]),"r"(a[2]),"r"(a[3]),"r"(b[0]),"r"(b[1]));
}
__device__ __forceinline__ void ldsm4(unsigned* d, unsigned addr){
  asm volatile("ldmatrix.sync.aligned.m8n8.x4.shared.b16 {%0,%1,%2,%3}, [%4];"
    : "=r"(d[0]),"=r"(d[1]),"=r"(d[2]),"=r"(d[3]) : "r"(addr));
}
__device__ __forceinline__ void ldsm4t(unsigned* d, unsigned addr){
  asm volatile("ldmatrix.sync.aligned.m8n8.x4.trans.shared.b16 {%0,%1,%2,%3}, [%4];"
    : "=r"(d[0]),"=r"(d[1]),"=r"(d[2]),"=r"(d[3]) : "r"(addr));
}
__device__ __forceinline__ void cpa16(unsigned dst, const void* src){
  asm volatile("cp.async.cg.shared.global [%0], [%1], 16;" :: "r"(dst), "l"(src));
}
#define CP_COMMIT asm volatile("cp.async.commit_group;")
#define CP_WAIT   asm volatile("cp.async.wait_group 0;")

// one double-buffered stage of 3-pass hi/lo mma over K=32 (2 ks steps)
// aH/aL/bH/bL: smem u32 addrs incl. warp m_base/n_base and lane offsets
__device__ __forceinline__ void mma_stage(unsigned aH, unsigned aL,
    unsigned bH, unsigned bL, float (&acc)[4][4][4]){
  #pragma unroll
  for (int ks=0; ks<2; ks++){
    unsigned kA = ks*32;                 // 16 elems * 2B along A cols
    unsigned kB = ks*16*(PCHB*2);        // 16 rows along B
    unsigned af[4][4], bh[8], bl[8];
    ldsm4t(&bh[0], bH + kB);
    ldsm4t(&bh[4], bH + kB + 32);        // n + 16 elems
    #pragma unroll
    for (int mi=0;mi<4;mi++) ldsm4(af[mi], aH + mi*(16*PCHA*2) + kA);
    #pragma unroll
    for (int mi=0;mi<4;mi++)
      #pragma unroll
      for (int ni=0;ni<4;ni++) mma16816(acc[mi][ni], af[mi], &bh[ni*2]);
    ldsm4t(&bl[0], bL + kB);
    ldsm4t(&bl[4], bL + kB + 32);
    #pragma unroll
    for (int mi=0;mi<4;mi++)
      #pragma unroll
      for (int ni=0;ni<4;ni++) mma16816(acc[mi][ni], af[mi], &bl[ni*2]);
    #pragma unroll
    for (int mi=0;mi<4;mi++) ldsm4(af[mi], aL + mi*(16*PCHA*2) + kA);
    #pragma unroll
    for (int mi=0;mi<4;mi++)
      #pragma unroll
      for (int ni=0;ni<4;ni++) mma16816(acc[mi][ni], af[mi], &bh[ni*2]);
  }
}

// ---- basis tables ----
__global__ void k_basis(){
  int idx = blockIdx.x*256 + threadIdx.x;
  if (idx >= MD*NN) return;
  int m = idx >> 13, n = idx & (NN-1);
  int p = (m*n) & (NN-1);
  float s, c;
  sincospif((float)p * (1.0f/4096.0f), &s, &c);
  bf ch,cl,sh,sl;
  f2bb(c,ch,cl); f2bb(s,sh,sl);
  int chn = n>>5, off = n&31;
  g_FblkH[(size_t)(chn*64 + m)*32 + off]      = ch;
  g_FblkL[(size_t)(chn*64 + m)*32 + off]      = cl;
  g_FblkH[(size_t)(chn*64 + 32 + m)*32 + off] = sh;
  g_FblkL[(size_t)(chn*64 + 32 + m)*32 + off] = sl;
  g_FnmH[(size_t)n*64 + m]      = ch;
  g_FnmL[(size_t)n*64 + m]      = cl;
  g_FnmH[(size_t)n*64 + 32 + m] = sh;
  g_FnmL[(size_t)n*64 + 32 + m] = sl;
}

// ---- transpose spectral weights (fp32, for mix) ----
__global__ void k_spec_t(const float* __restrict__ wr, const float* __restrict__ wi){
  int idx = blockIdx.x*256 + threadIdx.x;
  if (idx >= NL*MD*WD*WD) return;
  int o = idx & 127;
  int t = idx >> 7;
  int i = t & 127; t >>= 7;
  int m = t & 31;  int l = t >> 5;
  int src = ((l*WD + i)*WD + o)*MD + m;
  g_wrT[idx] = wr[src];
  g_wiT[idx] = wi[src];
}

// ---- convert skip_w and fc1_w to bf16 hi/lo (natural [k][o] layout) ----
__global__ void k_prep(const float* __restrict__ skw, const float* __restrict__ w1){
  int idx = blockIdx.x*256 + threadIdx.x;
  if (idx < NL*WD*WD){
    bf h,l; f2bb(skw[idx],h,l);
    g_skwH[idx]=h; g_skwL[idx]=l;
  }
  if (idx < WD*WD){
    bf h,l; f2bb(w1[idx],h,l);
    g_w1H[idx]=h; g_w1L[idx]=l;
  }
}

// ---- fc0: h = x*w + b, stored bf16 hi/lo ----
__global__ void k_fc0(const float* __restrict__ x, const float* __restrict__ w,
                      const float* __restrict__ bb){
  int idx2 = blockIdx.x*256 + threadIdx.x;    // each handles 2 channels
  int base = idx2*2;
  int c = base & 127; int bn = base >> 7;
  float xv = x[bn];
  float v0 = xv*w[c]   + bb[c];
  float v1 = xv*w[c+1] + bb[c+1];
  bf h0,l0,h1,l1; f2bb(v0,h0,l0); f2bb(v1,h1,l1);
  ((__nv_bfloat162*)g_hh0)[idx2] = __nv_bfloat162(h0,h1);
  ((__nv_bfloat162*)g_hl0)[idx2] = __nv_bfloat162(l0,l1);
}

// ---- forward DFT (tensor cores, split-K, cp.async double-buffered) ----
__global__ __launch_bounds__(128) void k_fwd(const bf* __restrict__ hh,
                                             const bf* __restrict__ hl){
  extern __shared__ char smem[];
  unsigned sb = (unsigned)__cvta_generic_to_shared(smem);
  // offsets (bytes): A 64*40*2=5120/buf, B 32*136*2=8704/buf
  const unsigned oAH=0, oAL=10240, oBH=20480, oBL=37888;
  int ck = blockIdx.x, b = blockIdx.y;
  int tid = threadIdx.x, wid = tid>>5, lane = tid&31, g = lane>>2, tg = lane&3;
  int n_base = wid*32;
  int r8 = (lane&7) + 8*((lane>>3)&1);
  int c8 = 8*(lane>>4);
  unsigned laneA = (unsigned)(r8*PCHA + c8)*2;
  unsigned laneB = (unsigned)(r8*PCHB + c8)*2;
  int n0 = ck*NPC;
  const bf* srcB_H = hh + ((size_t)b*NN + n0)*WD;
  const bf* srcB_L = hl + ((size_t)b*NN + n0)*WD;
  float acc[4][4][4];
  #pragma unroll
  for (int mi=0;mi<4;mi++)
    #pragma unroll
    for (int ni=0;ni<4;ni++)
      #pragma unroll
      for (int q=0;q<4;q++) acc[mi][ni][q]=0.f;

  #define FWD_FILL(s) { \
    int st = (s)&1; \
    unsigned aH = sb + oAH + st*5120, aL = sb + oAL + st*5120; \
    unsigned bH = sb + oBH + st*8704, bL = sb + oBL + st*8704; \
    const bf* aSrcH = g_FblkH + (size_t)(ck*8 + (s))*2048; \
    const bf* aSrcL = g_FblkL + (size_t)(ck*8 + (s))*2048; \
    _Pragma("unroll") \
    for (int j=0;j<2;j++){ \
      int idx = tid + j*128; int row = idx>>2, q = idx&3; \
      cpa16(aH + row*(PCHA*2) + q*16, aSrcH + idx*8); \
      cpa16(aL + row*(PCHA*2) + q*16, aSrcL + idx*8); \
    } \
    _Pragma("unroll") \
    for (int j=0;j<4;j++){ \
      int idx = tid + j*128; int row = idx>>4, q = idx&15; \
      cpa16(bH + row*(PCHB*2) + q*16, srcB_H + (size_t)(s)*32*WD + idx*8); \
      cpa16(bL + row*(PCHB*2) + q*16, srcB_L + (size_t)(s)*32*WD + idx*8); \
    } }

  FWD_FILL(0); CP_COMMIT;
  for (int i=0;i<8;i++){
    CP_WAIT; __syncthreads();
    if (i<7){ FWD_FILL(i+1); CP_COMMIT; }
    int st = i&1;
    mma_stage(sb+oAH+st*5120+laneA, sb+oAL+st*5120+laneA,
              sb+oBH+st*8704 + (unsigned)n_base*2 + laneB,
              sb+oBL+st*8704 + (unsigned)n_base*2 + laneB, acc);
  }
  #undef FWD_FILL

  float* dst = g_Xp + (size_t)(b*CHK+ck)*64*WD;
  #pragma unroll
  for (int ni=0;ni<4;ni++){
    int col = n_base + ni*8 + tg*2;
    #pragma unroll
    for (int mi=0;mi<4;mi++){
      int r0 = mi*16 + g;
      *(float2*)&dst[r0*WD+col]     = make_float2(acc[mi][ni][0], acc[mi][ni][1]);
      *(float2*)&dst[(r0+8)*WD+col] = make_float2(acc[mi][ni][2], acc[mi][ni][3]);
    }
  }
}

// ---- fused reduce + spectral mix; writes Y as bf16 hi/lo [b][j][o], sign folded ----
__global__ __launch_bounds__(128) void k_mix(int l){
  int m = blockIdx.x, b = blockIdx.y;
  int o = threadIdx.x;
  __shared__ float xr[128], xs[128];
  float sr=0.f, ss=0.f;
  #pragma unroll 8
  for (int c=0;c<CHK;c++){
    const float* p = g_Xp + (size_t)(b*CHK+c)*64*WD;
    sr += p[m*WD + o];
    ss += p[(MD+m)*WD + o];
  }
  xr[o]=sr; xs[o]=ss;
  __syncthreads();
  const float* wr = g_wrT + ((size_t)l*MD + m)*WD*WD + o;
  const float* wi = g_wiT + ((size_t)l*MD + m)*WD*WD + o;
  float yr=0.f, yi=0.f;
  #pragma unroll 8
  for (int i=0;i<WD;i++){
    float a = xr[i], s = xs[i];
    float r = wr[(size_t)i*WD], q = wi[(size_t)i*WD];
    yr += a*r + s*q;
    yi += a*q - s*r;
  }
  float alpha = (m==0) ? (1.0f/NN) : (2.0f/NN);
  bf h0,l0,h1,l1;
  f2bb(alpha*yr, h0, l0);
  f2bb(-alpha*yi, h1, l1);
  g_YbH[(size_t)(b*64+m)*WD+o]    = h0;
  g_YbL[(size_t)(b*64+m)*WD+o]    = l0;
  g_YbH[(size_t)(b*64+MD+m)*WD+o] = h1;
  g_YbL[(size_t)(b*64+MD+m)*WD+o] = l1;
}

// ---- fused layer: h_new = gelu?( h@skip_w + irfft(Y) + skip_b ), K=192 ----
__global__ __launch_bounds__(256) void k_layer(
      const bf* __restrict__ hh, const bf* __restrict__ hl,
      const float* __restrict__ skb,
      bf* __restrict__ ohh, bf* __restrict__ ohl, int l, int dogelu){
  extern __shared__ char smem[];
  unsigned sb = (unsigned)__cvta_generic_to_shared(smem);
  const unsigned oAH=0, oAL=20480, oBH=40960, oBL=58368;  // A 10240/buf, B 8704/buf
  int b = blockIdx.y;
  int n0 = blockIdx.x * 128;
  int tid = threadIdx.x, wid = tid>>5, lane = tid&31, g = lane>>2, tg = lane&3;
  int m_base = (wid>>2)*64, n_base = (wid&3)*32;
  int r8 = (lane&7) + 8*((lane>>3)&1);
  int c8 = 8*(lane>>4);
  unsigned laneA = (unsigned)(r8*PCHA + c8)*2;
  unsigned laneB = (unsigned)(r8*PCHB + c8)*2;
  float acc[4][4][4];
  #pragma unroll
  for (int mi=0;mi<4;mi++)
    #pragma unroll
    for (int ni=0;ni<4;ni++)
      #pragma unroll
      for (int q=0;q<4;q++) acc[mi][ni][q]=0.f;

  #define LAY_FILL(s) { \
    int st = (s)&1; int k0 = (s)*32; \
    unsigned aH = sb + oAH + st*10240, aL = sb + oAL + st*10240; \
    unsigned bH = sb + oBH + st*8704,  bL = sb + oBL + st*8704; \
    _Pragma("unroll") \
    for (int j=0;j<2;j++){ \
      int idx = tid + j*256; int row = idx>>2, q = idx&3; \
      const bf *sH, *sL; \
      if (k0 < 128){ \
        size_t off = ((size_t)b*NN + n0 + row)*WD + k0 + q*8; \
        sH = hh + off; sL = hl + off; \
      } else { \
        size_t off = (size_t)(n0+row)*64 + (k0-128) + q*8; \
        sH = g_FnmH + off; sL = g_FnmL + off; \
      } \
      cpa16(aH + row*(PCHA*2) + q*16, sH); \
      cpa16(aL + row*(PCHA*2) + q*16, sL); \
    } \
    _Pragma("unroll") \
    for (int j=0;j<2;j++){ \
      int idx = tid + j*256; int row = idx>>4, q = idx&15; \
      const bf *sH, *sL; \
      if (k0 < 128){ \
        size_t off = (size_t)l*16384 + (size_t)(k0+row)*WD + q*8; \
        sH = g_skwH + off; sL = g_skwL + off; \
      } else { \
        size_t off = (size_t)b*8192 + (size_t)(k0-128+row)*WD + q*8; \
        sH = g_YbH + off; sL = g_YbL + off; \
      } \
      cpa16(bH + row*(PCHB*2) + q*16, sH); \
      cpa16(bL + row*(PCHB*2) + q*16, sL); \
    } }

  LAY_FILL(0); CP_COMMIT;
  for (int i=0;i<6;i++){
    CP_WAIT; __syncthreads();
    if (i<5){ LAY_FILL(i+1); CP_COMMIT; }
    int st = i&1;
    mma_stage(sb+oAH+st*10240 + (unsigned)m_base*(PCHA*2) + laneA,
              sb+oAL+st*10240 + (unsigned)m_base*(PCHA*2) + laneA,
              sb+oBH+st*8704 + (unsigned)n_base*2 + laneB,
              sb+oBL+st*8704 + (unsigned)n_base*2 + laneB, acc);
  }
  #undef LAY_FILL

  #pragma unroll
  for (int ni=0;ni<4;ni++){
    int col = n_base + ni*8 + tg*2;
    float bia0 = skb[col], bia1 = skb[col+1];
    #pragma unroll
    for (int mi=0;mi<4;mi++){
      int r0 = n0 + m_base + mi*16 + g;
      float v0=acc[mi][ni][0]+bia0, v1=acc[mi][ni][1]+bia1;
      float v2=acc[mi][ni][2]+bia0, v3=acc[mi][ni][3]+bia1;
      if (dogelu){ v0=gelu_f(v0); v1=gelu_f(v1); v2=gelu_f(v2); v3=gelu_f(v3); }
      bf h0,l0,h1,l1;
      f2bb(v0,h0,l0); f2bb(v1,h1,l1);
      *(__nv_bfloat162*)&ohh[((size_t)b*NN + r0)*WD + col] = __nv_bfloat162(h0,h1);
      *(__nv_bfloat162*)&ohl[((size_t)b*NN + r0)*WD + col] = __nv_bfloat162(l0,l1);
      f2bb(v2,h0,l0); f2bb(v3,h1,l1);
      *(__nv_bfloat162*)&ohh[((size_t)b*NN + r0 + 8)*WD + col] = __nv_bfloat162(h0,h1);
      *(__nv_bfloat162*)&ohl[((size_t)b*NN + r0 + 8)*WD + col] = __nv_bfloat162(l0,l1);
    }
  }
}

// ---- head: out = gelu(h@fc1_w + fc1_b) @ fc2_w + fc2_b ----
__global__ __launch_bounds__(256) void k_head(
      const bf* __restrict__ hh, const bf* __restrict__ hl,
      const float* __restrict__ b1v, const float* __restrict__ w2,
      const float* __restrict__ b2v, float* __restrict__ out){
  extern __shared__ char smem[];
  unsigned sb = (unsigned)__cvta_generic_to_shared(smem);
  const unsigned oAH=0, oAL=20480, oBH=40960, oBL=58368;
  __shared__ float red[4][128];
  int row0 = blockIdx.x * 128;
  int tid = threadIdx.x, wid = tid>>5, lane = tid&31, g = lane>>2, tg = lane&3;
  int m_base = (wid>>2)*64, n_base = (wid&3)*32;
  int r8 = (lane&7) + 8*((lane>>3)&1);
  int c8 = 8*(lane>>4);
  unsigned laneA = (unsigned)(r8*PCHA + c8)*2;
  unsigned laneB = (unsigned)(r8*PCHB + c8)*2;
  float acc[4][4][4];
  #pragma unroll
  for (int mi=0;mi<4;mi++)
    #pragma unroll
    for (int ni=0;ni<4;ni++)
      #pragma unroll
      for (int q=0;q<4;q++) acc[mi][ni][q]=0.f;

  #define HEAD_FILL(s) { \
    int st = (s)&1; int k0 = (s)*32; \
    unsigned aH = sb + oAH + st*10240, aL = sb + oAL + st*10240; \
    unsigned bH = sb + oBH + st*8704,  bL = sb + oBL + st*8704; \
    _Pragma("unroll") \
    for (int j=0;j<2;j++){ \
      int idx = tid + j*256; int row = idx>>2, q = idx&3; \
      size_t off = ((size_t)row0 + row)*WD + k0 + q*8; \
      cpa16(aH + row*(PCHA*2) + q*16, hh + off); \
      cpa16(aL + row*(PCHA*2) + q*16, hl + off); \
    } \
    _Pragma("unroll") \
    for (int j=0;j<2;j++){ \
      int idx = tid + j*256; int row = idx>>4, q = idx&15; \
      size_t off = (size_t)(k0+row)*WD + q*8; \
      cpa16(bH + row*(PCHB*2) + q*16, g_w1H + off); \
      cpa16(bL + row*(PCHB*2) + q*16, g_w1L + off); \
    } }

  HEAD_FILL(0); CP_COMMIT;
  for (int i=0;i<4;i++){
    CP_WAIT; __syncthreads();
    if (i<3){ HEAD_FILL(i+1); CP_COMMIT; }
    int st = i&1;
    mma_stage(sb+oAH+st*10240 + (unsigned)m_base*(PCHA*2) + laneA,
              sb+oAL+st*10240 + (unsigned)m_base*(PCHA*2) + laneA,
              sb+oBH+st*8704 + (unsigned)n_base*2 + laneB,
              sb+oBL+st*8704 + (unsigned)n_base*2 + laneB, acc);
  }
  #undef HEAD_FILL

  float s[4][2];
  #pragma unroll
  for (int mi=0;mi<4;mi++){ s[mi][0]=0.f; s[mi][1]=0.f; }
  #pragma unroll
  for (int ni=0;ni<4;ni++){
    int col = n_base + ni*8 + tg*2;
    float bia0=b1v[col], bia1=b1v[col+1];
    float w20=w2[col],  w21=w2[col+1];
    #pragma unroll
    for (int mi=0;mi<4;mi++){
      s[mi][0] += gelu_f(acc[mi][ni][0]+bia0)*w20 + gelu_f(acc[mi][ni][1]+bia1)*w21;
      s[mi][1] += gelu_f(acc[mi][ni][2]+bia0)*w20 + gelu_f(acc[mi][ni][3]+bia1)*w21;
    }
  }
  #pragma unroll
  for (int mi=0;mi<4;mi++){
    #pragma unroll
    for (int q=0;q<2;q++){
      s[mi][q] += __shfl_xor_sync(0xffffffffu, s[mi][q], 1);
      s[mi][q] += __shfl_xor_sync(0xffffffffu, s[mi][q], 2);
    }
  }
  __syncthreads();
  if (tg == 0){
    int wn = wid & 3;
    #pragma unroll
    for (int mi=0;mi<4;mi++){
      red[wn][m_base+mi*16+g]   = s[mi][0];
      red[wn][m_base+mi*16+g+8] = s[mi][1];
    }
  }
  __syncthreads();
  if (tid < 128)
    out[row0 + tid] = red[0][tid]+red[1][tid]+red[2][tid]+red[3][tid] + b2v[0];
}

extern "C" void kernel_launch(void* const* d_in, const int* in_sizes, int n_in,
                              void* d_out, int out_size){
  const float* x       = (const float*)d_in[0];
  const float* fc0_w   = (const float*)d_in[1];
  const float* fc0_b   = (const float*)d_in[2];
  const float* spec_wr = (const float*)d_in[3];
  const float* spec_wi = (const float*)d_in[4];
  const float* skip_w  = (const float*)d_in[5];
  const float* skip_b  = (const float*)d_in[6];
  const float* fc1_w   = (const float*)d_in[7];
  const float* fc1_b   = (const float*)d_in[8];
  const float* fc2_w   = (const float*)d_in[9];
  const float* fc2_b   = (const float*)d_in[10];
  float* out = (float*)d_out;
  (void)in_sizes; (void)n_in; (void)out_size;

  static int attr_done = 0;
  if (!attr_done){
    cudaFuncSetAttribute(k_fwd,   cudaFuncAttributeMaxDynamicSharedMemorySize, 55296);
    cudaFuncSetAttribute(k_layer, cudaFuncAttributeMaxDynamicSharedMemorySize, 75776);
    cudaFuncSetAttribute(k_head,  cudaFuncAttributeMaxDynamicSharedMemorySize, 75776);
    attr_done = 1;
  }

  void *ph0, *pl0, *ph1, *pl1;
  cudaGetSymbolAddress(&ph0, g_hh0);
  cudaGetSymbolAddress(&pl0, g_hl0);
  cudaGetSymbolAddress(&ph1, g_hh1);
  cudaGetSymbolAddress(&pl1, g_hl1);
  bf* hinH = (bf*)ph0; bf* hinL = (bf*)pl0;
  bf* houtH = (bf*)ph1; bf* houtL = (bf*)pl1;

  k_basis<<<(MD*NN + 255)/256, 256>>>();
  k_spec_t<<<(NL*MD*WD*WD + 255)/256, 256>>>(spec_wr, spec_wi);
  k_prep<<<(NL*WD*WD + 255)/256, 256>>>(skip_w, fc1_w);
  k_fc0<<<(Bq*NN*WD/2)/256, 256>>>(x, fc0_w, fc0_b);

  for (int l=0; l<NL; l++){
    k_fwd<<<dim3(CHK, Bq), 128, 55296>>>(hinH, hinL);
    k_mix<<<dim3(MD, Bq), 128>>>(l);
    k_layer<<<dim3(NN/128, Bq), 256, 75776>>>(hinH, hinL,
        skip_b + (size_t)l*WD, houtH, houtL, l, (l < NL-1) ? 1 : 0);
    bf* t;
    t = hinH; hinH = houtH; houtH = t;
    t = hinL; hinL = houtL; houtL = t;
  }
  k_head<<<(Bq*NN)/128, 256, 75776>>>(hinH, hinL, fc1_b, fc2_w, fc2_b, out);
}

// round 5
// speedup vs baseline: 3.0001x; 1.0062x over previous
#include <cuda_runtime.h>
#include <cuda_bf16.h>
#include <math.h>

#define Bq 16
#define NN 8192
#define WD 128
#define MD 32
#define NL 4
#define PCHA 40        // A smem pitch (bf16): 16B-aligned rows, conflict-free ldmatrix
#define PCHB 136       // B smem pitch

typedef __nv_bfloat16 bf;

// ---- static device scratch ----
__device__ __align__(16) bf g_hh0[Bq*NN*WD];
__device__ __align__(16) bf g_hl0[Bq*NN*WD];
__device__ __align__(16) bf g_hh1[Bq*NN*WD];
__device__ __align__(16) bf g_hl1[Bq*NN*WD];
__device__ __align__(16) bf g_FblkH[64*NN];   // [n-chunk32][64 r][32]
__device__ __align__(16) bf g_FblkL[64*NN];
__device__ __align__(16) bf g_FnmH[NN*64];    // [n][r]
__device__ __align__(16) bf g_FnmL[NN*64];
__device__ __align__(16) bf g_skwH[NL*WD*WD];
__device__ __align__(16) bf g_skwL[NL*WD*WD];
__device__ __align__(16) bf g_w1H[WD*WD];
__device__ __align__(16) bf g_w1L[WD*WD];
__device__ __align__(16) bf g_YbH[Bq*64*WD];  // [b][j][o]: j<32: Yr', j>=32: -Yi'
__device__ __align__(16) bf g_YbL[Bq*64*WD];
__device__ float g_Xp[Bq*64*64*WD];           // split-K partials, 64 chunks (33.5MB)
__device__ float g_X0[Bq*64];                 // layer-0 x-DFT: [b][r] (cos rows, sin rows)
__device__ float g_wrT[NL*MD*WD*WD];
__device__ float g_wiT[NL*MD*WD*WD];

__device__ __forceinline__ void f2bb(float x, bf &h, bf &l){
  h = __float2bfloat16(x);
  l = __float2bfloat16(x - __bfloat162float(h));
}
__device__ __forceinline__ float gelu_f(float v){
  return 0.5f*v*(1.0f + erff(v*0.70710678118654752f));
}
__device__ __forceinline__ void mma16816(float* d, const unsigned* a, const unsigned* b){
  asm volatile("mma.sync.aligned.m16n8k16.row.col.f32.bf16.bf16.f32 "
    "{%0,%1,%2,%3},{%4,%5,%6,%7},{%8,%9},{%0,%1,%2,%3};\n"
    : "+f"(d[0]),"+f"(d[1]),"+f"(d[2]),"+f"(d[3])
    : "r"(a[0]),"r"(a[1]),"r"(a[2]),"r"(a[3]),"r"(b[0]),"r"(b[1]));
}
__device__ __forceinline__ void ldsm4(unsigned* d, unsigned addr){
  asm volatile("ldmatrix.sync.aligned.m8n8.x4.shared.b16 {%0,%1,%2,%3}, [%4];"
    : "=r"(d[0]),"=r"(d[1]),"=r"(d[2]),"=r"(d[3]) : "r"(addr));
}
__device__ __forceinline__ void ldsm4t(unsigned* d, unsigned addr){
  asm volatile("ldmatrix.sync.aligned.m8n8.x4.trans.shared.b16 {%0,%1,%2,%3}, [%4];"
    : "=r"(d[0]),"=r"(d[1]),"=r"(d[2]),"=r"(d[3]) : "r"(addr));
}
__device__ __forceinline__ void cpa16(unsigned dst, const void* src){
  asm volatile("cp.async.cg.shared.global [%0], [%1], 16;" :: "r"(dst), "l"(src));
}
#define CP_COMMIT asm volatile("cp.async.commit_group;")
#define CP_WAIT   asm volatile("cp.async.wait_group 0;")

// 3-pass hi/lo mma over K=32: 4 mi x 4 ni (warp tile 64x32)
__device__ __forceinline__ void mma_stage(unsigned aH, unsigned aL,
    unsigned bH, unsigned bL, float (&acc)[4][4][4]){
  #pragma unroll
  for (int ks=0; ks<2; ks++){
    unsigned kA = ks*32;
    unsigned kB = ks*16*(PCHB*2);
    unsigned af[4][4], bh[8], bl[8];
    ldsm4t(&bh[0], bH + kB);
    ldsm4t(&bh[4], bH + kB + 32);
    #pragma unroll
    for (int mi=0;mi<4;mi++) ldsm4(af[mi], aH + mi*(16*PCHA*2) + kA);
    #pragma unroll
    for (int mi=0;mi<4;mi++)
      #pragma unroll
      for (int ni=0;ni<4;ni++) mma16816(acc[mi][ni], af[mi], &bh[ni*2]);
    ldsm4t(&bl[0], bL + kB);
    ldsm4t(&bl[4], bL + kB + 32);
    #pragma unroll
    for (int mi=0;mi<4;mi++)
      #pragma unroll
      for (int ni=0;ni<4;ni++) mma16816(acc[mi][ni], af[mi], &bl[ni*2]);
    #pragma unroll
    for (int mi=0;mi<4;mi++) ldsm4(af[mi], aL + mi*(16*PCHA*2) + kA);
    #pragma unroll
    for (int mi=0;mi<4;mi++)
      #pragma unroll
      for (int ni=0;ni<4;ni++) mma16816(acc[mi][ni], af[mi], &bh[ni*2]);
  }
}

// 3-pass hi/lo mma over K=32: 4 mi x 2 ni (warp tile 64x16) for fused fwd-DFT
__device__ __forceinline__ void mma_stage2(unsigned aH, unsigned aL,
    unsigned bH, unsigned bL, float (&acc)[4][2][4]){
  #pragma unroll
  for (int ks=0; ks<2; ks++){
    unsigned kA = ks*32;
    unsigned kB = ks*16*(PCHB*2);
    unsigned af[4][4], bh[4], bl[4];
    ldsm4t(&bh[0], bH + kB);
    #pragma unroll
    for (int mi=0;mi<4;mi++) ldsm4(af[mi], aH + mi*(16*PCHA*2) + kA);
    #pragma unroll
    for (int mi=0;mi<4;mi++)
      #pragma unroll
      for (int ni=0;ni<2;ni++) mma16816(acc[mi][ni], af[mi], &bh[ni*2]);
    ldsm4t(&bl[0], bL + kB);
    #pragma unroll
    for (int mi=0;mi<4;mi++)
      #pragma unroll
      for (int ni=0;ni<2;ni++) mma16816(acc[mi][ni], af[mi], &bl[ni*2]);
    #pragma unroll
    for (int mi=0;mi<4;mi++) ldsm4(af[mi], aL + mi*(16*PCHA*2) + kA);
    #pragma unroll
    for (int mi=0;mi<4;mi++)
      #pragma unroll
      for (int ni=0;ni<2;ni++) mma16816(acc[mi][ni], af[mi], &bh[ni*2]);
  }
}

// ---- basis tables ----
__global__ void k_basis(){
  int idx = blockIdx.x*256 + threadIdx.x;
  if (idx >= MD*NN) return;
  int m = idx >> 13, n = idx & (NN-1);
  int p = (m*n) & (NN-1);
  float s, c;
  sincospif((float)p * (1.0f/4096.0f), &s, &c);
  bf ch,cl,sh,sl;
  f2bb(c,ch,cl); f2bb(s,sh,sl);
  int chn = n>>5, off = n&31;
  g_FblkH[(size_t)(chn*64 + m)*32 + off]      = ch;
  g_FblkL[(size_t)(chn*64 + m)*32 + off]      = cl;
  g_FblkH[(size_t)(chn*64 + 32 + m)*32 + off] = sh;
  g_FblkL[(size_t)(chn*64 + 32 + m)*32 + off] = sl;
  g_FnmH[(size_t)n*64 + m]      = ch;
  g_FnmL[(size_t)n*64 + m]      = cl;
  g_FnmH[(size_t)n*64 + 32 + m] = sh;
  g_FnmL[(size_t)n*64 + 32 + m] = sl;
}

// ---- transpose spectral weights (fp32, for mix) ----
__global__ void k_spec_t(const float* __restrict__ wr, const float* __restrict__ wi){
  int idx = blockIdx.x*256 + threadIdx.x;
  if (idx >= NL*MD*WD*WD) return;
  int o = idx & 127;
  int t = idx >> 7;
  int i = t & 127; t >>= 7;
  int m = t & 31;  int l = t >> 5;
  int src = ((l*WD + i)*WD + o)*MD + m;
  g_wrT[idx] = wr[src];
  g_wiT[idx] = wi[src];
}

// ---- convert skip_w and fc1_w to bf16 hi/lo ----
__global__ void k_prep(const float* __restrict__ skw, const float* __restrict__ w1){
  int idx = blockIdx.x*256 + threadIdx.x;
  if (idx < NL*WD*WD){
    bf h,l; f2bb(skw[idx],h,l);
    g_skwH[idx]=h; g_skwL[idx]=l;
  }
  if (idx < WD*WD){
    bf h,l; f2bb(w1[idx],h,l);
    g_w1H[idx]=h; g_w1L[idx]=l;
  }
}

// ---- fc0: h = x*w + b, bf16 hi/lo, 8 channels/thread ----
__global__ void k_fc0(const float* __restrict__ x, const float* __restrict__ w,
                      const float* __restrict__ bb){
  int idx = blockIdx.x*256 + threadIdx.x;     // Bq*NN*WD/8 total
  int base = idx*8;
  int c = base & 127; int bn = base >> 7;
  float xv = x[bn];
  float4 w0 = *(const float4*)&w[c], w1 = *(const float4*)&w[c+4];
  float4 b0 = *(const float4*)&bb[c], b1 = *(const float4*)&bb[c+4];
  float v[8] = { xv*w0.x+b0.x, xv*w0.y+b0.y, xv*w0.z+b0.z, xv*w0.w+b0.w,
                 xv*w1.x+b1.x, xv*w1.y+b1.y, xv*w1.z+b1.z, xv*w1.w+b1.w };
  __nv_bfloat162 hh[4], ll[4];
  #pragma unroll
  for (int q=0;q<4;q++){
    bf h0,l0,h1,l1; f2bb(v[q*2],h0,l0); f2bb(v[q*2+1],h1,l1);
    hh[q] = __nv_bfloat162(h0,h1); ll[q] = __nv_bfloat162(l0,l1);
  }
  *(uint4*)&g_hh0[base] = *(uint4*)hh;
  *(uint4*)&g_hl0[base] = *(uint4*)ll;
}

// ---- layer-0 forward DFT of x (rank-1 factorization), fp32 exact ----
__global__ __launch_bounds__(256) void k_fwd0(const float* __restrict__ x){
  int r = blockIdx.x, b = blockIdx.y, t = threadIdx.x;
  int m = r & 31; bool iscos = (r < 32);
  const float* xb = x + (size_t)b*NN;
  float s = 0.f;
  for (int n = t; n < NN; n += 256){
    int p = (m*n) & (NN-1);
    float sn, cs; sincospif((float)p*(1.0f/4096.0f), &sn, &cs);
    s += (iscos ? cs : sn) * xb[n];
  }
  __shared__ float red[256];
  red[t] = s; __syncthreads();
  for (int o=128;o>0;o>>=1){ if (t<o) red[t]+=red[t+o]; __syncthreads(); }
  if (t==0) g_X0[b*64+r] = red[0];
}

// ---- fused reduce + spectral mix; Y as bf16 hi/lo, sign folded ----
__global__ __launch_bounds__(128) void k_mix(int l, const float* __restrict__ fc0w,
                                             const float* __restrict__ fc0b){
  int m = blockIdx.x, b = blockIdx.y;
  int o = threadIdx.x;
  __shared__ float xr[128], xs[128];
  float sr, ss;
  if (l == 0){
    float xc = g_X0[b*64+m], xsn = g_X0[b*64+MD+m];
    float w = fc0w[o];
    sr = xc*w + (m==0 ? (float)NN*fc0b[o] : 0.f);
    ss = xsn*w;
  } else {
    sr = 0.f; ss = 0.f;
    #pragma unroll 8
    for (int c=0;c<64;c++){
      const float* p = g_Xp + (size_t)(b*64+c)*64*WD;
      sr += p[m*WD + o];
      ss += p[(MD+m)*WD + o];
    }
  }
  xr[o]=sr; xs[o]=ss;
  __syncthreads();
  const float* wr = g_wrT + ((size_t)l*MD + m)*WD*WD + o;
  const float* wi = g_wiT + ((size_t)l*MD + m)*WD*WD + o;
  float yr=0.f, yi=0.f;
  #pragma unroll 8
  for (int i=0;i<WD;i++){
    float a = xr[i], s = xs[i];
    float r = wr[(size_t)i*WD], q = wi[(size_t)i*WD];
    yr += a*r + s*q;
    yi += a*q - s*r;
  }
  float alpha = (m==0) ? (1.0f/NN) : (2.0f/NN);
  bf h0,l0,h1,l1;
  f2bb(alpha*yr, h0, l0);
  f2bb(-alpha*yi, h1, l1);
  g_YbH[(size_t)(b*64+m)*WD+o]    = h0;
  g_YbL[(size_t)(b*64+m)*WD+o]    = l0;
  g_YbH[(size_t)(b*64+MD+m)*WD+o] = h1;
  g_YbL[(size_t)(b*64+MD+m)*WD+o] = l1;
}

// ---- fused layer: h_new = gelu?(h@skip_w + irfft(Y) + skip_b), K=192,
//      then (dofwd) forward-DFT of h_new tile -> split-K partials g_Xp ----
// dynamic smem layout (bytes), total 90112:
//  main:  AH 0..20480 (2x10240), AL 20480..40960, BH 40960..58368 (2x8704), BL 58368..75776
//  post:  HT_H 0..34816 (h tile hi, [128 rows][PCHB]), HT_L 34816..69632,
//         A2: H0 69632, L0 74752, H1 79872, L1 84992 (each 5120)
__global__ __launch_bounds__(256,2) void k_layer(
      const bf* __restrict__ hh, const bf* __restrict__ hl,
      const float* __restrict__ skb,
      bf* __restrict__ ohh, bf* __restrict__ ohl, int l, int dogelu, int dofwd){
  extern __shared__ char smem[];
  unsigned sb = (unsigned)__cvta_generic_to_shared(smem);
  const unsigned oAH=0, oAL=20480, oBH=40960, oBL=58368;
  const unsigned oHTH=0, oHTL=34816, oA2=69632;
  int b = blockIdx.y;
  int n0 = blockIdx.x * 128;
  int tid = threadIdx.x, wid = tid>>5, lane = tid&31, g = lane>>2, tg = lane&3;
  int m_base = (wid>>2)*64, n_base = (wid&3)*32;
  int r8 = (lane&7) + 8*((lane>>3)&1);
  int c8 = 8*(lane>>4);
  unsigned laneA = (unsigned)(r8*PCHA + c8)*2;
  unsigned laneB = (unsigned)(r8*PCHB + c8)*2;
  float acc[4][4][4];
  #pragma unroll
  for (int mi=0;mi<4;mi++)
    #pragma unroll
    for (int ni=0;ni<4;ni++)
      #pragma unroll
      for (int q=0;q<4;q++) acc[mi][ni][q]=0.f;

  #define LAY_FILL(s) { \
    int st = (s)&1; int k0 = (s)*32; \
    unsigned aH = sb + oAH + st*10240, aL = sb + oAL + st*10240; \
    unsigned bH = sb + oBH + st*8704,  bL = sb + oBL + st*8704; \
    _Pragma("unroll") \
    for (int j=0;j<2;j++){ \
      int idx = tid + j*256; int row = idx>>2, q = idx&3; \
      const bf *sH, *sL; \
      if (k0 < 128){ \
        size_t off = ((size_t)b*NN + n0 + row)*WD + k0 + q*8; \
        sH = hh + off; sL = hl + off; \
      } else { \
        size_t off = (size_t)(n0+row)*64 + (k0-128) + q*8; \
        sH = g_FnmH + off; sL = g_FnmL + off; \
      } \
      cpa16(aH + row*(PCHA*2) + q*16, sH); \
      cpa16(aL + row*(PCHA*2) + q*16, sL); \
    } \
    _Pragma("unroll") \
    for (int j=0;j<2;j++){ \
      int idx = tid + j*256; int row = idx>>4, q = idx&15; \
      const bf *sH, *sL; \
      if (k0 < 128){ \
        size_t off = (size_t)l*16384 + (size_t)(k0+row)*WD + q*8; \
        sH = g_skwH + off; sL = g_skwL + off; \
      } else { \
        size_t off = (size_t)b*8192 + (size_t)(k0-128+row)*WD + q*8; \
        sH = g_YbH + off; sL = g_YbL + off; \
      } \
      cpa16(bH + row*(PCHB*2) + q*16, sH); \
      cpa16(bL + row*(PCHB*2) + q*16, sL); \
    } }

  LAY_FILL(0); CP_COMMIT;
  for (int i=0;i<6;i++){
    CP_WAIT; __syncthreads();
    if (i<5){ LAY_FILL(i+1); CP_COMMIT; }
    int st = i&1;
    mma_stage(sb+oAH+st*10240 + (unsigned)m_base*(PCHA*2) + laneA,
              sb+oAL+st*10240 + (unsigned)m_base*(PCHA*2) + laneA,
              sb+oBH+st*8704 + (unsigned)n_base*2 + laneB,
              sb+oBL+st*8704 + (unsigned)n_base*2 + laneB, acc);
  }
  #undef LAY_FILL
  __syncthreads();   // all warps done reading main smem before reuse

  // epilogue: bias+gelu, store to gmem hi/lo, and stash tile in smem for fwd-DFT
  bf* htH = (bf*)(smem + oHTH);
  bf* htL = (bf*)(smem + oHTL);
  #pragma unroll
  for (int ni=0;ni<4;ni++){
    int col = n_base + ni*8 + tg*2;
    float bia0 = skb[col], bia1 = skb[col+1];
    #pragma unroll
    for (int mi=0;mi<4;mi++){
      int rl = m_base + mi*16 + g;
      int r0 = n0 + rl;
      float v0=acc[mi][ni][0]+bia0, v1=acc[mi][ni][1]+bia1;
      float v2=acc[mi][ni][2]+bia0, v3=acc[mi][ni][3]+bia1;
      if (dogelu){ v0=gelu_f(v0); v1=gelu_f(v1); v2=gelu_f(v2); v3=gelu_f(v3); }
      bf h0,l0,h1,l1;
      f2bb(v0,h0,l0); f2bb(v1,h1,l1);
      *(__nv_bfloat162*)&ohh[((size_t)b*NN + r0)*WD + col] = __nv_bfloat162(h0,h1);
      *(__nv_bfloat162*)&ohl[((size_t)b*NN + r0)*WD + col] = __nv_bfloat162(l0,l1);
      if (dofwd){
        *(__nv_bfloat162*)&htH[rl*PCHB + col] = __nv_bfloat162(h0,h1);
        *(__nv_bfloat162*)&htL[rl*PCHB + col] = __nv_bfloat162(l0,l1);
      }
      f2bb(v2,h0,l0); f2bb(v3,h1,l1);
      *(__nv_bfloat162*)&ohh[((size_t)b*NN + r0 + 8)*WD + col] = __nv_bfloat162(h0,h1);
      *(__nv_bfloat162*)&ohl[((size_t)b*NN + r0 + 8)*WD + col] = __nv_bfloat162(l0,l1);
      if (dofwd){
        *(__nv_bfloat162*)&htH[(rl+8)*PCHB + col] = __nv_bfloat162(h0,h1);
        *(__nv_bfloat162*)&htL[(rl+8)*PCHB + col] = __nv_bfloat162(l0,l1);
      }
    }
  }
  if (!dofwd) return;

  // second GEMM: Xp_partial[64 r][128 c] = F_chunk x h_tile, K=128 in 4 stages
  float acc2[4][2][4];
  #pragma unroll
  for (int mi=0;mi<4;mi++)
    #pragma unroll
    for (int ni=0;ni<2;ni++)
      #pragma unroll
      for (int q=0;q<4;q++) acc2[mi][ni][q]=0.f;

  #define A2_FILL(s) { \
    int st = (s)&1; \
    unsigned aH = sb + oA2 + st*10240, aL = aH + 5120; \
    const bf* srcH = g_FblkH + (size_t)(blockIdx.x*4 + (s))*2048; \
    const bf* srcL = g_FblkL + (size_t)(blockIdx.x*4 + (s))*2048; \
    { int row = tid>>2, q = tid&3; \
      cpa16(aH + row*(PCHA*2) + q*16, srcH + tid*8); \
      cpa16(aL + row*(PCHA*2) + q*16, srcL + tid*8); } }

  A2_FILL(0); CP_COMMIT;
  unsigned bHbase = sb + oHTH + (unsigned)(wid*16)*2 + laneB;
  unsigned bLbase = sb + oHTL + (unsigned)(wid*16)*2 + laneB;
  for (int s=0;s<4;s++){
    CP_WAIT; __syncthreads();
    if (s<3){ A2_FILL(s+1); CP_COMMIT; }
    int st = s&1;
    mma_stage2(sb + oA2 + st*10240 + laneA,
               sb + oA2 + st*10240 + 5120 + laneA,
               bHbase + (unsigned)(s*32)*(PCHB*2),
               bLbase + (unsigned)(s*32)*(PCHB*2), acc2);
  }
  #undef A2_FILL

  float* dst = g_Xp + (size_t)(b*64 + blockIdx.x)*64*WD;
  #pragma unroll
  for (int ni=0;ni<2;ni++){
    int col = wid*16 + ni*8 + tg*2;
    #pragma unroll
    for (int mi=0;mi<4;mi++){
      int r0 = mi*16 + g;
      *(float2*)&dst[r0*WD+col]     = make_float2(acc2[mi][ni][0], acc2[mi][ni][1]);
      *(float2*)&dst[(r0+8)*WD+col] = make_float2(acc2[mi][ni][2], acc2[mi][ni][3]);
    }
  }
}

// ---- head: out = gelu(h@fc1_w + fc1_b) @ fc2_w + fc2_b ----
__global__ __launch_bounds__(256) void k_head(
      const bf* __restrict__ hh, const bf* __restrict__ hl,
      const float* __restrict__ b1v, const float* __restrict__ w2,
      const float* __restrict__ b2v, float* __restrict__ out){
  extern __shared__ char smem[];
  unsigned sb = (unsigned)__cvta_generic_to_shared(smem);
  const unsigned oAH=0, oAL=20480, oBH=40960, oBL=58368;
  __shared__ float red[4][128];
  int row0 = blockIdx.x * 128;
  int tid = threadIdx.x, wid = tid>>5, lane = tid&31, g = lane>>2, tg = lane&3;
  int m_base = (wid>>2)*64, n_base = (wid&3)*32;
  int r8 = (lane&7) + 8*((lane>>3)&1);
  int c8 = 8*(lane>>4);
  unsigned laneA = (unsigned)(r8*PCHA + c8)*2;
  unsigned laneB = (unsigned)(r8*PCHB + c8)*2;
  float acc[4][4][4];
  #pragma unroll
  for (int mi=0;mi<4;mi++)
    #pragma unroll
    for (int ni=0;ni<4;ni++)
      #pragma unroll
      for (int q=0;q<4;q++) acc[mi][ni][q]=0.f;

  #define HEAD_FILL(s) { \
    int st = (s)&1; int k0 = (s)*32; \
    unsigned aH = sb + oAH + st*10240, aL = sb + oAL + st*10240; \
    unsigned bH = sb + oBH + st*8704,  bL = sb + oBL + st*8704; \
    _Pragma("unroll") \
    for (int j=0;j<2;j++){ \
      int idx = tid + j*256; int row = idx>>2, q = idx&3; \
      size_t off = ((size_t)row0 + row)*WD + k0 + q*8; \
      cpa16(aH + row*(PCHA*2) + q*16, hh + off); \
      cpa16(aL + row*(PCHA*2) + q*16, hl + off); \
    } \
    _Pragma("unroll") \
    for (int j=0;j<2;j++){ \
      int idx = tid + j*256; int row = idx>>4, q = idx&15; \
      size_t off = (size_t)(k0+row)*WD + q*8; \
      cpa16(bH + row*(PCHB*2) + q*16, g_w1H + off); \
      cpa16(bL + row*(PCHB*2) + q*16, g_w1L + off); \
    } }

  HEAD_FILL(0); CP_COMMIT;
  for (int i=0;i<4;i++){
    CP_WAIT; __syncthreads();
    if (i<3){ HEAD_FILL(i+1); CP_COMMIT; }
    int st = i&1;
    mma_stage(sb+oAH+st*10240 + (unsigned)m_base*(PCHA*2) + laneA,
              sb+oAL+st*10240 + (unsigned)m_base*(PCHA*2) + laneA,
              sb+oBH+st*8704 + (unsigned)n_base*2 + laneB,
              sb+oBL+st*8704 + (unsigned)n_base*2 + laneB, acc);
  }
  #undef HEAD_FILL

  float s[4][2];
  #pragma unroll
  for (int mi=0;mi<4;mi++){ s[mi][0]=0.f; s[mi][1]=0.f; }
  #pragma unroll
  for (int ni=0;ni<4;ni++){
    int col = n_base + ni*8 + tg*2;
    float bia0=b1v[col], bia1=b1v[col+1];
    float w20=w2[col],  w21=w2[col+1];
    #pragma unroll
    for (int mi=0;mi<4;mi++){
      s[mi][0] += gelu_f(acc[mi][ni][0]+bia0)*w20 + gelu_f(acc[mi][ni][1]+bia1)*w21;
      s[mi][1] += gelu_f(acc[mi][ni][2]+bia0)*w20 + gelu_f(acc[mi][ni][3]+bia1)*w21;
    }
  }
  #pragma unroll
  for (int mi=0;mi<4;mi++){
    #pragma unroll
    for (int q=0;q<2;q++){
      s[mi][q] += __shfl_xor_sync(0xffffffffu, s[mi][q], 1);
      s[mi][q] += __shfl_xor_sync(0xffffffffu, s[mi][q], 2);
    }
  }
  __syncthreads();
  if (tg == 0){
    int wn = wid & 3;
    #pragma unroll
    for (int mi=0;mi<4;mi++){
      red[wn][m_base+mi*16+g]   = s[mi][0];
      red[wn][m_base+mi*16+g+8] = s[mi][1];
    }
  }
  __syncthreads();
  if (tid < 128)
    out[row0 + tid] = red[0][tid]+red[1][tid]+red[2][tid]+red[3][tid] + b2v[0];
}

extern "C" void kernel_launch(void* const* d_in, const int* in_sizes, int n_in,
                              void* d_out, int out_size){
  const float* x       = (const float*)d_in[0];
  const float* fc0_w   = (const float*)d_in[1];
  const float* fc0_b   = (const float*)d_in[2];
  const float* spec_wr = (const float*)d_in[3];
  const float* spec_wi = (const float*)d_in[4];
  const float* skip_w  = (const float*)d_in[5];
  const float* skip_b  = (const float*)d_in[6];
  const float* fc1_w   = (const float*)d_in[7];
  const float* fc1_b   = (const float*)d_in[8];
  const float* fc2_w   = (const float*)d_in[9];
  const float* fc2_b   = (const float*)d_in[10];
  float* out = (float*)d_out;
  (void)in_sizes; (void)n_in; (void)out_size;

  static int attr_done = 0;
  if (!attr_done){
    cudaFuncSetAttribute(k_layer, cudaFuncAttributeMaxDynamicSharedMemorySize, 90112);
    cudaFuncSetAttribute(k_head,  cudaFuncAttributeMaxDynamicSharedMemorySize, 75776);
    attr_done = 1;
  }

  void *ph0, *pl0, *ph1, *pl1;
  cudaGetSymbolAddress(&ph0, g_hh0);
  cudaGetSymbolAddress(&pl0, g_hl0);
  cudaGetSymbolAddress(&ph1, g_hh1);
  cudaGetSymbolAddress(&pl1, g_hl1);
  bf* hinH = (bf*)ph0; bf* hinL = (bf*)pl0;
  bf* houtH = (bf*)ph1; bf* houtL = (bf*)pl1;

  k_basis<<<(MD*NN + 255)/256, 256>>>();
  k_spec_t<<<(NL*MD*WD*WD + 255)/256, 256>>>(spec_wr, spec_wi);
  k_prep<<<(NL*WD*WD + 255)/256, 256>>>(skip_w, fc1_w);
  k_fc0<<<(Bq*NN*WD/8)/256, 256>>>(x, fc0_w, fc0_b);
  k_fwd0<<<dim3(64, Bq), 256>>>(x);

  for (int l=0; l<NL; l++){
    k_mix<<<dim3(MD, Bq), 128>>>(l, fc0_w, fc0_b);
    k_layer<<<dim3(NN/128, Bq), 256, 90112>>>(hinH, hinL,
        skip_b + (size_t)l*WD, houtH, houtL, l,
        (l < NL-1) ? 1 : 0, (l < NL-1) ? 1 : 0);
    bf* t;
    t = hinH; hinH = houtH; houtH = t;
    t = hinL; hinL = houtL; houtL = t;
  }
  k_head<<<(Bq*NN)/128, 256, 75776>>>(hinH, hinL, fc1_b, fc2_w, fc2_b, out);
}